// round 11
// baseline (speedup 1.0000x reference)
#include <cuda_runtime.h>
#include <cuda_bf16.h>
#include <math.h>

#define TIMESTEPS 1000
#define BB 4
#define NN 2048
#define EE (NN * (NN - 1) / 2)   // 2096128
#define NSLOT_B (EE / 4)         // 524032 slots per batch
#define NSLOT_PAD (1 << 19)      // 524288 padded
#define NSLOT_TOT (BB * NSLOT_PAD) // 2^21
#define NTHREADS 320
#define NBLKS 740                // 148 SMs * 5 blocks (one wave at 40 regs)
#define NWARPS (NTHREADS / 32)

__device__ double g_part[NBLKS];
__device__ unsigned int g_count = 0;

__device__ __forceinline__ float elem_loss(
    int a, float uu, float qa,
    float flip_e, float one_m_fe,
    float qt00, float qt01, float qt10, float qt11)
{
    const float p1 = a ? one_m_fe : flip_e;
    const bool  x  = (uu < p1);
    const float qt = a ? (x ? qt11 : qt10)
                       : (x ? qt01 : qt00);
    const float sp = __logf(1.0f + __expf(qa));   // softplus(q); |q| small (N(0,1))
    return fmaf(-qa, qt, sp);
}

__global__ __launch_bounds__(NTHREADS, 5) void diffusion_loss_kernel(
    const int* __restrict__ adj,
    const int* __restrict__ t,
    const float* __restrict__ u,
    const float* __restrict__ q,
    float* __restrict__ out)
{
    const int tid = threadIdx.x;

    // per-batch constants once per block
    __shared__ float sC[BB][6];   // {flip_e, 1-flip_e, qt00, qt01, qt10, qt11}
    if (tid < BB) {
        const int tb = t[tid];
        const float ln098 = -0.0202027073175194484f;          // ln(0.98)
        const float flip_e = 0.5f * (1.0f - __expf((float)(tb + 1) * ln098));
        const int   tp     = (tb == 0) ? (TIMESTEPS - 1) : (tb - 1);  // JAX wrap Qt[-1]->Qt[999]
        const float flip_p = 0.5f * (1.0f - __expf((float)(tp + 1) * ln098));
        const float flip0  = 0.01f;
        const float one_m_fe = 1.0f - flip_e;
        const float one_m_fp = 1.0f - flip_p;
        const float one_m_f0 = 1.0f - flip0;
        sC[tid][0] = flip_e;
        sC[tid][1] = one_m_fe;
        sC[tid][2] = flip0    * flip_p   / one_m_fe;   // qt00
        sC[tid][3] = one_m_f0 * flip_p   / flip_e;     // qt01
        sC[tid][4] = flip0    * one_m_fp / flip_e;     // qt10
        sC[tid][5] = one_m_f0 * one_m_fp / one_m_fe;   // qt11
    }
    __syncthreads();

    const int T = NBLKS * NTHREADS;     // 236800
    float s = 0.0f;

    for (int sl = blockIdx.x * NTHREADS + tid; sl < NSLOT_TOT; sl += T) {
        const int b  = sl >> 19;
        const int es = sl & (NSLOT_PAD - 1);
        if (es >= NSLOT_B) continue;            // padded dead slots
        const int e0 = es << 2;                 // first of 4 consecutive edge indices

        const float flip_e   = sC[b][0];
        const float one_m_fe = sC[b][1];
        const float qt00     = sC[b][2];
        const float qt01     = sC[b][3];
        const float qt10     = sC[b][4];
        const float qt11     = sC[b][5];

        const int*   A = adj + b * (NN * NN);
        const float* U = u   + b * (NN * NN);
        const float* Q = q   + b * EE;

        // decode row i of e0: i = floor((1+sqrt(8e+1))/2); fp32 exact (8e+1 < 2^24)
        const float fe = (float)e0;
        int i = (int)((1.0f + sqrtf(fmaf(8.0f, fe, 1.0f))) * 0.5f);
        int tri = (i * (i - 1)) >> 1;
        if (tri > e0)            { i -= 1; tri -= i; }
        else if (tri + i <= e0)  { tri += i; i += 1; }
        int j = e0 - tri;

        // precompute the 4 (row,col) element addresses (single-step row advance)
        int i0 = i,        j0 = j;
        int i1 = i0, j1 = j0 + 1; if (j1 >= i1) { j1 = 0; i1 += 1; }
        int i2 = i1, j2 = j1 + 1; if (j2 >= i2) { j2 = 0; i2 += 1; }
        int i3 = i2, j3 = j2 + 1; if (j3 >= i3) { j3 = 0; i3 += 1; }
        const int e_0 = i0 * NN + j0;
        const int e_1 = i1 * NN + j1;
        const int e_2 = i2 * NN + j2;
        const int e_3 = i3 * NN + j3;

        // front-batched loads: 1 vec4 q (aligned) + 4 adj + 4 u
        const float4 qv = *(const float4*)(Q + e0);
        const int   a0 = A[e_0], a1 = A[e_1], a2 = A[e_2], a3 = A[e_3];
        const float u0 = U[e_0], u1 = U[e_1], u2 = U[e_2], u3 = U[e_3];

        s += elem_loss(a0, u0, qv.x, flip_e, one_m_fe, qt00, qt01, qt10, qt11);
        s += elem_loss(a1, u1, qv.y, flip_e, one_m_fe, qt00, qt01, qt10, qt11);
        s += elem_loss(a2, u2, qv.z, flip_e, one_m_fe, qt00, qt01, qt10, qt11);
        s += elem_loss(a3, u3, qv.w, flip_e, one_m_fe, qt00, qt01, qt10, qt11);
    }

    // block reduce (10 warps)
    for (int off = 16; off > 0; off >>= 1)
        s += __shfl_down_sync(0xFFFFFFFFu, s, off);
    __shared__ float warp_sums[NWARPS];
    const int lane = tid & 31;
    const int wid  = tid >> 5;
    if (lane == 0) warp_sums[wid] = s;
    __syncthreads();
    if (wid == 0) {
        float w = (lane < NWARPS) ? warp_sums[lane] : 0.0f;
        for (int off = 16; off > 0; off >>= 1)
            w += __shfl_down_sync(0xFFFFFFFFu, w, off);
        if (lane == 0) g_part[blockIdx.x] = (double)w;
    }

    // last-block final reduction (counter reset -> graph-replay safe)
    __shared__ bool is_last;
    __threadfence();
    __syncthreads();
    if (tid == 0) {
        unsigned int c = atomicAdd(&g_count, 1u);
        is_last = (c == (unsigned int)(NBLKS - 1));
    }
    __syncthreads();
    if (is_last) {
        double ds = 0.0;
        for (int i2_ = tid; i2_ < NBLKS; i2_ += NTHREADS)
            ds += g_part[i2_];
        for (int off = 16; off > 0; off >>= 1)
            ds += __shfl_down_sync(0xFFFFFFFFu, ds, off);
        __shared__ double dwarp[NWARPS];
        if (lane == 0) dwarp[wid] = ds;
        __syncthreads();
        if (wid == 0) {
            double dv = (lane < NWARPS) ? dwarp[lane] : 0.0;
            for (int off = 16; off > 0; off >>= 1)
                dv += __shfl_down_sync(0xFFFFFFFFu, dv, off);
            if (lane == 0) {
                out[0] = (float)(dv / (double)((size_t)BB * EE));
                g_count = 0;
            }
        }
    }
}

extern "C" void kernel_launch(void* const* d_in, const int* in_sizes, int n_in,
                              void* d_out, int out_size)
{
    const int*   adj = (const int*)d_in[0];    // (B,N,N) int32
    const int*   t   = (const int*)d_in[1];    // (B,)    int32
    const float* u   = (const float*)d_in[2];  // (B,N,N) float32
    const float* q   = (const float*)d_in[3];  // (B,E)   float32
    float* out = (float*)d_out;

    diffusion_loss_kernel<<<NBLKS, NTHREADS>>>(adj, t, u, q, out);
}

// round 12
// speedup vs baseline: 1.1792x; 1.1792x over previous
#include <cuda_runtime.h>
#include <cuda_bf16.h>
#include <math.h>

#define TIMESTEPS 1000
#define BB 4
#define NN 2048
#define EE (NN * (NN - 1) / 2)   // 2096128
#define NTASK (1024 * BB)        // 4096 row-pair tasks
#define NBLKS 592                // 148 SMs * 4 blocks (one wave at <=64 regs)
#define NTHREADS 256

__device__ double g_part[NBLKS];
__device__ unsigned int g_count = 0;

__device__ __forceinline__ float elem_loss(
    int a, float uu, float qa,
    float flip_e, float one_m_fe,
    float qt00, float qt01, float qt10, float qt11)
{
    const float p1 = a ? one_m_fe : flip_e;
    const bool  x  = (uu < p1);
    const float qt = a ? (x ? qt11 : qt10)
                       : (x ? qt01 : qt00);
    const float sp = __logf(1.0f + __expf(qa));   // softplus(q); |q| small (N(0,1))
    return fmaf(-qa, qt, sp);
}

// task geometry (pair bk within batch b)
struct Geo {
    int  eo0, eo1, qo0, qo1;   // vec4-slot offsets
    int  eT, qT;               // tail element (-1 if none)
    bool d0, d1;
    int  b;
};

__device__ __forceinline__ Geo make_geo(int tk, int tid)
{
    Geo g;
    const int bk = tk & 1023;
    g.b = tk >> 10;
    const int r1 = bk + 1;
    const int r2 = 2047 - bk;
    const bool same = (r1 == r2);

    const int n1 = r1 >> 2;
    const int n2 = same ? 0 : (r2 >> 2);
    const int G  = n1 + n2;
    const int t1 = r1 & 3;
    const int t2 = same ? 0 : (r2 & 3);

    const int eA1 = r1 * NN;
    const int eA2 = r2 * NN - (n1 << 2);
    const int qA1 = (r1 * (r1 - 1)) >> 1;
    const int qA2 = ((r2 * (r2 - 1)) >> 1) - (n1 << 2);

    const int g0 = tid;
    const int g1 = tid + NTHREADS;
    g.d0 = (g0 < G);
    g.d1 = (g1 < G);
    g.eo0 = g.eo1 = g.qo0 = g.qo1 = 0;
    if (g.d0) {
        const bool lo = g0 < n1;
        g.eo0 = (lo ? eA1 : eA2) + (g0 << 2);
        g.qo0 = (lo ? qA1 : qA2) + (g0 << 2);
    }
    if (g.d1) {
        const bool lo = g1 < n1;
        g.eo1 = (lo ? eA1 : eA2) + (g1 << 2);
        g.qo1 = (lo ? qA1 : qA2) + (g1 << 2);
    }
    g.eT = -1; g.qT = 0;
    if (tid < t1 + t2) {
        const bool lo = tid < t1;
        const int row = lo ? r1 : r2;
        const int k   = lo ? ((n1 << 2) + tid) : ((n2 << 2) + (tid - t1));
        g.eT = row * NN + k;
        g.qT = ((row * (row - 1)) >> 1) + k;
    }
    return g;
}

__global__ __launch_bounds__(NTHREADS, 4) void diffusion_loss_kernel(
    const int* __restrict__ adj,
    const int* __restrict__ t,
    const float* __restrict__ u,
    const float* __restrict__ q,
    float* __restrict__ out)
{
    const int tid = threadIdx.x;

    __shared__ float sC[BB][6];   // {flip_e, 1-flip_e, qt00, qt01, qt10, qt11}
    if (tid < BB) {
        const int tb = t[tid];
        const float ln098 = -0.0202027073175194484f;          // ln(0.98)
        const float flip_e = 0.5f * (1.0f - __expf((float)(tb + 1) * ln098));
        const int   tp     = (tb == 0) ? (TIMESTEPS - 1) : (tb - 1);  // JAX wrap Qt[-1]->Qt[999]
        const float flip_p = 0.5f * (1.0f - __expf((float)(tp + 1) * ln098));
        const float flip0  = 0.01f;
        const float one_m_fe = 1.0f - flip_e;
        const float one_m_fp = 1.0f - flip_p;
        const float one_m_f0 = 1.0f - flip0;
        sC[tid][0] = flip_e;
        sC[tid][1] = one_m_fe;
        sC[tid][2] = flip0    * flip_p   / one_m_fe;
        sC[tid][3] = one_m_f0 * flip_p   / flip_e;
        sC[tid][4] = flip0    * one_m_fp / flip_e;
        sC[tid][5] = one_m_f0 * one_m_fp / one_m_fe;
    }
    __syncthreads();

    float s = 0.0f;

    for (int tk = blockIdx.x; tk < NTASK; tk += 2 * NBLKS) {
        const int  tkB  = tk + NBLKS;
        const bool hasB = (tkB < NTASK);

        // ---- geometry for both tasks ----
        const Geo gA = make_geo(tk, tid);
        Geo gB; gB.d0 = gB.d1 = false; gB.eT = -1; gB.b = 0;
        gB.eo0 = gB.eo1 = gB.qo0 = gB.qo1 = gB.qT = 0;
        if (hasB) gB = make_geo(tkB, tid);

        const int*   Aa = adj + gA.b * (NN * NN);
        const float* Ua = u   + gA.b * (NN * NN);
        const float* Qa = q   + gA.b * EE;
        const int*   Ab = adj + gB.b * (NN * NN);
        const float* Ub = u   + gB.b * (NN * NN);
        const float* Qb = q   + gB.b * EE;

        // ---- front-batched loads for BOTH tasks (up to 24 LDGs in flight) ----
        int4 a0A, a1A, a0B, a1B;
        float4 u0A, u1A, u0B, u1B;
        float qA0[4], qA1_[4], qB0[4], qB1[4];

        if (gA.d0) {
            a0A = *(const int4*)(Aa + gA.eo0);
            u0A = *(const float4*)(Ua + gA.eo0);
            qA0[0] = Qa[gA.qo0]; qA0[1] = Qa[gA.qo0+1]; qA0[2] = Qa[gA.qo0+2]; qA0[3] = Qa[gA.qo0+3];
        }
        if (gA.d1) {
            a1A = *(const int4*)(Aa + gA.eo1);
            u1A = *(const float4*)(Ua + gA.eo1);
            qA1_[0] = Qa[gA.qo1]; qA1_[1] = Qa[gA.qo1+1]; qA1_[2] = Qa[gA.qo1+2]; qA1_[3] = Qa[gA.qo1+3];
        }
        if (gB.d0) {
            a0B = *(const int4*)(Ab + gB.eo0);
            u0B = *(const float4*)(Ub + gB.eo0);
            qB0[0] = Qb[gB.qo0]; qB0[1] = Qb[gB.qo0+1]; qB0[2] = Qb[gB.qo0+2]; qB0[3] = Qb[gB.qo0+3];
        }
        if (gB.d1) {
            a1B = *(const int4*)(Ab + gB.eo1);
            u1B = *(const float4*)(Ub + gB.eo1);
            qB1[0] = Qb[gB.qo1]; qB1[1] = Qb[gB.qo1+1]; qB1[2] = Qb[gB.qo1+2]; qB1[3] = Qb[gB.qo1+3];
        }

        // ---- compute task A ----
        {
            const float fe = sC[gA.b][0], ofe = sC[gA.b][1];
            const float c0 = sC[gA.b][2], c1 = sC[gA.b][3], c2 = sC[gA.b][4], c3 = sC[gA.b][5];
            if (gA.d0) {
                s += elem_loss(a0A.x, u0A.x, qA0[0], fe, ofe, c0, c1, c2, c3);
                s += elem_loss(a0A.y, u0A.y, qA0[1], fe, ofe, c0, c1, c2, c3);
                s += elem_loss(a0A.z, u0A.z, qA0[2], fe, ofe, c0, c1, c2, c3);
                s += elem_loss(a0A.w, u0A.w, qA0[3], fe, ofe, c0, c1, c2, c3);
            }
            if (gA.d1) {
                s += elem_loss(a1A.x, u1A.x, qA1_[0], fe, ofe, c0, c1, c2, c3);
                s += elem_loss(a1A.y, u1A.y, qA1_[1], fe, ofe, c0, c1, c2, c3);
                s += elem_loss(a1A.z, u1A.z, qA1_[2], fe, ofe, c0, c1, c2, c3);
                s += elem_loss(a1A.w, u1A.w, qA1_[3], fe, ofe, c0, c1, c2, c3);
            }
            if (gA.eT >= 0)
                s += elem_loss(Aa[gA.eT], Ua[gA.eT], Qa[gA.qT], fe, ofe, c0, c1, c2, c3);
        }
        // ---- compute task B ----
        if (hasB) {
            const float fe = sC[gB.b][0], ofe = sC[gB.b][1];
            const float c0 = sC[gB.b][2], c1 = sC[gB.b][3], c2 = sC[gB.b][4], c3 = sC[gB.b][5];
            if (gB.d0) {
                s += elem_loss(a0B.x, u0B.x, qB0[0], fe, ofe, c0, c1, c2, c3);
                s += elem_loss(a0B.y, u0B.y, qB0[1], fe, ofe, c0, c1, c2, c3);
                s += elem_loss(a0B.z, u0B.z, qB0[2], fe, ofe, c0, c1, c2, c3);
                s += elem_loss(a0B.w, u0B.w, qB0[3], fe, ofe, c0, c1, c2, c3);
            }
            if (gB.d1) {
                s += elem_loss(a1B.x, u1B.x, qB1[0], fe, ofe, c0, c1, c2, c3);
                s += elem_loss(a1B.y, u1B.y, qB1[1], fe, ofe, c0, c1, c2, c3);
                s += elem_loss(a1B.z, u1B.z, qB1[2], fe, ofe, c0, c1, c2, c3);
                s += elem_loss(a1B.w, u1B.w, qB1[3], fe, ofe, c0, c1, c2, c3);
            }
            if (gB.eT >= 0)
                s += elem_loss(Ab[gB.eT], Ub[gB.eT], Qb[gB.qT], fe, ofe, c0, c1, c2, c3);
        }
    }

    // block reduce
    for (int off = 16; off > 0; off >>= 1)
        s += __shfl_down_sync(0xFFFFFFFFu, s, off);
    __shared__ float warp_sums[NTHREADS / 32];
    const int lane = tid & 31;
    const int wid  = tid >> 5;
    if (lane == 0) warp_sums[wid] = s;
    __syncthreads();
    if (wid == 0) {
        float w = (lane < (NTHREADS >> 5)) ? warp_sums[lane] : 0.0f;
        for (int off = 4; off > 0; off >>= 1)
            w += __shfl_down_sync(0xFFFFFFFFu, w, off);
        if (lane == 0) g_part[blockIdx.x] = (double)w;
    }

    // last-block final reduction (counter reset -> graph-replay safe)
    __shared__ bool is_last;
    __threadfence();
    __syncthreads();
    if (tid == 0) {
        unsigned int c = atomicAdd(&g_count, 1u);
        is_last = (c == (unsigned int)(NBLKS - 1));
    }
    __syncthreads();
    if (is_last) {
        double ds = 0.0;
        for (int i = tid; i < NBLKS; i += NTHREADS)
            ds += g_part[i];
        for (int off = 16; off > 0; off >>= 1)
            ds += __shfl_down_sync(0xFFFFFFFFu, ds, off);
        __shared__ double dwarp[NTHREADS / 32];
        if (lane == 0) dwarp[wid] = ds;
        __syncthreads();
        if (wid == 0) {
            double dv = (lane < (NTHREADS >> 5)) ? dwarp[lane] : 0.0;
            for (int off = 4; off > 0; off >>= 1)
                dv += __shfl_down_sync(0xFFFFFFFFu, dv, off);
            if (lane == 0) {
                out[0] = (float)(dv / (double)((size_t)BB * EE));
                g_count = 0;
            }
        }
    }
}

extern "C" void kernel_launch(void* const* d_in, const int* in_sizes, int n_in,
                              void* d_out, int out_size)
{
    const int*   adj = (const int*)d_in[0];    // (B,N,N) int32
    const int*   t   = (const int*)d_in[1];    // (B,)    int32
    const float* u   = (const float*)d_in[2];  // (B,N,N) float32
    const float* q   = (const float*)d_in[3];  // (B,E)   float32
    float* out = (float*)d_out;

    diffusion_loss_kernel<<<NBLKS, NTHREADS>>>(adj, t, u, q, out);
}